// round 13
// baseline (speedup 1.0000x reference)
#include <cuda_runtime.h>
#include <cuda_bf16.h>
#include <math.h>
#include <stdint.h>

#define T_DIM 4096
#define D_DIM 1024
#define H_DIM 1024
#define B_MAX 8

#define CHUNKS 32
#define CLEN   (T_DIM / CHUNKS)   // 128

// ---------------- scratch (device globals) -----------------------------------
__device__ __align__(16) float2 g_lfv[(size_t)B_MAX * T_DIM * H_DIM];  // 268MB
__device__ float g_cA[(size_t)B_MAX * CHUNKS * H_DIM];
__device__ float g_cB[(size_t)B_MAX * CHUNKS * H_DIM];
__device__ float g_cS[(size_t)B_MAX * CHUNKS * H_DIM];
__device__ __align__(16) __nv_bfloat16 g_xbf[(size_t)B_MAX * T_DIM * D_DIM]; // 64MB
__device__ __align__(16) __nv_bfloat16 g_wbf[3][(size_t)H_DIM * D_DIM];      // 6MB

// ---------------- math helpers (MUFU fast path) --------------------------------
__device__ __forceinline__ float splus(float x) {
    return fmaxf(x, 0.0f) + __logf(1.0f + __expf(-fabsf(x)));
}
__device__ __forceinline__ float lae(float a, float b) {
    float m = fmaxf(a, b);
    float d = fabsf(a - b);
    return m + __logf(1.0f + __expf(-d));
}
__device__ __forceinline__ float log_g(float x) {
    return (x >= 0.0f) ? __logf(x + 0.5f) : -splus(-x);
}
__device__ __forceinline__ uint32_t bf16x2(float lo, float hi) {
    uint32_t r;
    asm("cvt.rn.bf16x2.f32 %0, %1, %2;" : "=r"(r) : "f"(hi), "f"(lo));
    return r;
}
__device__ __forceinline__ uint32_t smem_u32(const void* p) {
    uint32_t a;
    asm("{ .reg .u64 t; cvta.to.shared.u64 t, %1; cvt.u32.u64 %0, t; }" : "=r"(a) : "l"(p));
    return a;
}
__device__ __forceinline__ void st_cs_v2(float2* p, float a, float b) {
    asm volatile("st.global.cs.v2.f32 [%0], {%1,%2};" :: "l"(p), "f"(a), "f"(b) : "memory");
}
__device__ __forceinline__ float4 ld_cs_v4(const float4* p) {
    float4 v;
    asm volatile("ld.global.cs.v4.f32 {%0,%1,%2,%3}, [%4];"
                 : "=f"(v.x), "=f"(v.y), "=f"(v.z), "=f"(v.w) : "l"(p));
    return v;
}

// granule (row, kb) -> byte offset inside one operand tile (64B rows, rot-swizzle)
__device__ __forceinline__ uint32_t goff(int row, int kb) {
    return (uint32_t)(row * 64 + (((kb + (row >> 1)) & 3) << 4));
}

#define LDSM_X4(r0, r1, r2, r3, addr)                                            \
    asm volatile("ldmatrix.sync.aligned.m8n8.x4.shared.b16 {%0,%1,%2,%3}, [%4];" \
                 : "=r"(r0), "=r"(r1), "=r"(r2), "=r"(r3) : "r"(addr))

#define CP16(dst, src)                                                           \
    asm volatile("cp.async.cg.shared.global [%0], [%1], 16;"                     \
                 :: "r"(dst), "l"(src) : "memory")

// ---------------- merged convert fp32 -> bf16 (x then Wf,Wi,Wh) ----------------
__global__ void __launch_bounds__(256)
to_bf16_all(const float* __restrict__ x, const float* __restrict__ w0,
            const float* __restrict__ w1, const float* __restrict__ w2,
            size_t nx, size_t nw)
{
    const size_t i8 = ((size_t)blockIdx.x * blockDim.x + threadIdx.x) * 8;
    const float* src;
    __nv_bfloat16* dst;
    size_t off;
    if (i8 < nx) {
        src = x; dst = g_xbf; off = i8;
    } else {
        const size_t j = i8 - nx;
        const int gate = (int)(j / nw);
        off = j - (size_t)gate * nw;
        const float* ws[3] = {w0, w1, w2};
        src = ws[gate]; dst = g_wbf[gate];
    }
    float4 a = *(const float4*)(src + off);
    float4 b = *(const float4*)(src + off + 4);
    uint4 o;
    o.x = bf16x2(a.x, a.y);
    o.y = bf16x2(a.z, a.w);
    o.z = bf16x2(b.x, b.y);
    o.w = bf16x2(b.z, b.w);
    *(uint4*)(dst + off) = o;
}

// ---------------- bf16 TC fused 3-gate GEMM, 2 decoupled pipeline groups -------
#define BM 128
#define BN 64
#define BK 32
#define STAGES 4
#define GSTAGE_SZ 16384u    // per group per stage: A 4KB @0, W[g] 4KB @4096+g*4096
#define GROUP_SZ  (STAGES * GSTAGE_SZ)       // 64KB per group
#define GEMM_SMEM (2 * GROUP_SZ)             // 128KB

__global__ void __launch_bounds__(512, 1)
gemm_epi(const float* __restrict__ bf,
         const float* __restrict__ bi,
         const float* __restrict__ bh)
{
    extern __shared__ __align__(128) uint8_t smem[];
    const uint32_t sbase = smem_u32(smem);

    const int tid  = threadIdx.x;
    const int lane = tid & 31;
    const int wid  = tid >> 5;         // 0..15
    const int g    = lane >> 2;
    const int t    = lane & 3;

    const int group = wid >> 3;        // 0: rows 0-63, 1: rows 64-127
    const uint32_t gb = sbase + (uint32_t)group * GROUP_SZ;

    const int m0 = blockIdx.y * BM;
    const int n0 = blockIdx.x * BN;

    const int warpM = (wid >> 1) * 16;         // 0..112 step 16
    const int warpMloc = warpM & 63;
    const int warpN = (wid & 1) * 32;          // 0,32

    const int lrow = ((lane >> 3) & 1) * 8 + (lane & 7);
    const int lkb  = lane >> 4;
    const uint32_t aAddr = gb + goff(warpMloc + lrow, lkb);
    uint32_t bAddr[3][2];
#pragma unroll
    for (int gt = 0; gt < 3; gt++)
#pragma unroll
        for (int h = 0; h < 2; h++)
            bAddr[gt][h] = gb + 4096 + gt * 4096 + goff(warpN + h * 16 + lrow, lkb);

    const int ltid = tid & 255;
    const __nv_bfloat16* lsrc[4];
    uint32_t ldst[4];
#pragma unroll
    for (int j = 0; j < 4; j++) {
        const int q = ltid + j * 256;          // 0..1023
        if (q < 256) {
            const int row = q >> 2, kb = q & 3;
            lsrc[j] = g_xbf + (size_t)(m0 + group * 64 + row) * D_DIM + kb * 8;
            ldst[j] = gb + goff(row, kb);
        } else {
            const int p = q - 256;
            const int gate = p >> 8, row = (p >> 2) & 63, kb = p & 3;
            lsrc[j] = g_wbf[gate] + (size_t)(n0 + row) * D_DIM + kb * 8;
            ldst[j] = gb + 4096 + gate * 4096 + goff(row, kb);
        }
    }

    float acc[3][4][4];
#pragma unroll
    for (int gt = 0; gt < 3; gt++)
#pragma unroll
        for (int nt = 0; nt < 4; nt++)
#pragma unroll
            for (int c = 0; c < 4; c++) acc[gt][nt][c] = 0.0f;

    const int NT = D_DIM / BK;   // 32
    const int barid = group + 1;

#define LOAD_STAGE(st, kt)                                                     \
    {                                                                          \
        const uint32_t so = (uint32_t)(st) * GSTAGE_SZ;                        \
        const int ko = (kt) * BK;                                              \
        CP16(ldst[0] + so, lsrc[0] + ko);                                      \
        CP16(ldst[1] + so, lsrc[1] + ko);                                      \
        CP16(ldst[2] + so, lsrc[2] + ko);                                      \
        CP16(ldst[3] + so, lsrc[3] + ko);                                      \
    }

#pragma unroll
    for (int s = 0; s < STAGES - 1; s++) {
        LOAD_STAGE(s, s);
        asm volatile("cp.async.commit_group;" ::: "memory");
    }

    for (int kt = 0; kt < NT; kt++) {
        const uint32_t sel = (uint32_t)(kt % STAGES) * GSTAGE_SZ;

        asm volatile("cp.async.wait_group %0;" :: "n"(STAGES - 2) : "memory");
        asm volatile("bar.sync %0, 256;" :: "r"(barid) : "memory");

#pragma unroll
        for (int s = 0; s < 2; s++) {
            const uint32_t sx = (uint32_t)(s << 5);
            uint32_t a[4];
            LDSM_X4(a[0], a[1], a[2], a[3], (aAddr ^ sx) + sel);
#pragma unroll
            for (int gt = 0; gt < 3; gt++) {
                uint32_t bb[2][4];
#pragma unroll
                for (int h = 0; h < 2; h++)
                    LDSM_X4(bb[h][0], bb[h][1], bb[h][2], bb[h][3],
                            (bAddr[gt][h] ^ sx) + sel);
#pragma unroll
                for (int nt = 0; nt < 4; nt++) {
                    float* c = acc[gt][nt];
                    const uint32_t b0 = bb[nt >> 1][nt & 1];
                    const uint32_t b1 = bb[nt >> 1][(nt & 1) + 2];
                    asm volatile(
                        "mma.sync.aligned.m16n8k16.row.col.f32.bf16.bf16.f32 "
                        "{%0,%1,%2,%3}, {%4,%5,%6,%7}, {%8,%9}, {%0,%1,%2,%3};"
                        : "+f"(c[0]), "+f"(c[1]), "+f"(c[2]), "+f"(c[3])
                        : "r"(a[0]), "r"(a[1]), "r"(a[2]), "r"(a[3]),
                          "r"(b0), "r"(b1));
                }
            }
        }

        if (kt + STAGES - 1 < NT)
            LOAD_STAGE((kt + STAGES - 1) % STAGES, kt + STAGES - 1);
        asm volatile("cp.async.commit_group;" ::: "memory");
    }

    // ---- epilogue: bias + gate math -> g_lfv (streaming) + chunk aggregation --
    float* sF = (float*)smem;                     // [128][65]
    float* sV = (float*)(smem + 33280);           // [128][65]
    float* pA = (float*)(smem + 66560);           // [8][64]
    float* pB = (float*)(smem + 68608);

    float bfv[4][2], biv[4][2], bhv[4][2];
#pragma unroll
    for (int nt = 0; nt < 4; nt++)
#pragma unroll
        for (int e = 0; e < 2; e++) {
            const int n = n0 + warpN + nt * 8 + 2 * t + e;
            bfv[nt][e] = bf[n];
            biv[nt][e] = bi[n];
            bhv[nt][e] = bh[n];
        }

    __syncthreads();   // join both groups; all LDSM reads done before SMEM reuse

#pragma unroll
    for (int hh = 0; hh < 2; hh++) {
        const int lt = warpM + hh * 8 + g;
        const size_t rowoff = (size_t)(m0 + lt) * H_DIM + n0 + warpN;
#pragma unroll
        for (int nt = 0; nt < 4; nt++) {
#pragma unroll
            for (int e = 0; e < 2; e++) {
                const int ci = hh * 2 + e;
                float zf = acc[0][nt][ci] + bfv[nt][e];
                float zi = acc[1][nt][ci] + biv[nt][e];
                float zh = acc[2][nt][ci] + bhv[nt][e];
                float diff  = splus(-zf) - splus(-zi);
                float logF  = -splus(diff);
                float logV  = -splus(-diff) + log_g(zh);
                const int ln = warpN + nt * 8 + 2 * t + e;
                st_cs_v2(&g_lfv[rowoff + nt * 8 + 2 * t + e], logF, logV);
                sF[lt * 65 + ln] = logF;
                sV[lt * 65 + ln] = logV;
            }
        }
    }
    __syncthreads();

    // segmented scan: 64 cols x 8 segments of 16
    {
        const int col = tid & 63;
        const int seg = tid >> 6;
        const int base = seg * 16;
        float A  = sF[base * 65 + col];
        float Bv = sV[base * 65 + col];
#pragma unroll
        for (int i = 1; i < 16; i++) {
            const float a  = sF[(base + i) * 65 + col];
            const float b  = sV[(base + i) * 65 + col];
            A += a;
            Bv = lae(Bv + a, b);
        }
        pA[seg * 64 + col] = A;
        pB[seg * 64 + col] = Bv;
    }
    __syncthreads();

    if (tid < 64) {
        float A  = pA[tid];
        float Bv = pB[tid];
#pragma unroll
        for (int s = 1; s < 8; s++) {
            const float a = pA[s * 64 + tid];
            const float b = pB[s * 64 + tid];
            Bv = lae(Bv + a, b);
            A += a;
        }
        const size_t co = (size_t)blockIdx.y * H_DIM + n0 + tid;
        g_cA[co] = A;
        g_cB[co] = Bv;
    }
}

// ---------------- pass 2: scan across chunks (prefetch-then-scan) -------------
__global__ void __launch_bounds__(128)
scan_across(const float* __restrict__ h0, int B)
{
    const size_t gid = (size_t)blockIdx.x * blockDim.x + threadIdx.x;
    const int h = (int)(gid % H_DIM);
    const int b = (int)(gid / H_DIM);
    if (b >= B) return;

    const size_t base = (size_t)b * CHUNKS * H_DIM + h;

    float vA[CHUNKS], vB[CHUNKS];
#pragma unroll
    for (int c = 0; c < CHUNKS; c++) {
        vA[c] = g_cA[base + (size_t)c * H_DIM];
        vB[c] = g_cB[base + (size_t)c * H_DIM];
    }

    float state = log_g(h0[(size_t)b * H_DIM + h]);
#pragma unroll
    for (int c = 0; c < CHUNKS; c++) {
        g_cS[base + (size_t)c * H_DIM] = state;
        state = lae(state + vA[c], vB[c]);
    }
}

// ---------------- pass 3: final within-chunk scan + exp (4 cols/thread) -------
__global__ void __launch_bounds__(256)
scan_final(float* __restrict__ out, int B)
{
    const size_t gid = (size_t)blockIdx.x * blockDim.x + threadIdx.x;
    const int hq = (int)(gid % (H_DIM / 4));
    const int h  = hq * 4;
    const size_t bc = gid / (H_DIM / 4);
    const int c = (int)(bc % CHUNKS);
    const int b = (int)(bc / CHUNKS);
    if (b >= B) return;

    const size_t co = ((size_t)b * CHUNKS + c) * H_DIM + h;
    float s0 = g_cS[co];
    float s1 = g_cS[co + 1];
    float s2 = g_cS[co + 2];
    float s3 = g_cS[co + 3];

    size_t idx = ((size_t)b * T_DIM + (size_t)c * CLEN) * H_DIM + h;
#pragma unroll 4
    for (int tt = 0; tt < CLEN; tt++) {
        const float4 v0 = ld_cs_v4((const float4*)&g_lfv[idx]);     // {f0,v0,f1,v1}
        const float4 v1 = ld_cs_v4((const float4*)&g_lfv[idx + 2]); // {f2,v2,f3,v3}
        s0 = lae(s0 + v0.x, v0.y);
        s1 = lae(s1 + v0.z, v0.w);
        s2 = lae(s2 + v1.x, v1.y);
        s3 = lae(s3 + v1.z, v1.w);
        float4 ov;
        ov.x = __expf(s0);
        ov.y = __expf(s1);
        ov.z = __expf(s2);
        ov.w = __expf(s3);
        asm volatile("st.global.cs.v4.f32 [%0], {%1,%2,%3,%4};"
                     :: "l"(out + idx), "f"(ov.x), "f"(ov.y), "f"(ov.z), "f"(ov.w)
                     : "memory");
        idx += H_DIM;
    }
}

// ---------------- launch --------------------------------------------------------
extern "C" void kernel_launch(void* const* d_in, const int* in_sizes, int n_in,
                              void* d_out, int out_size)
{
    const float* x  = (const float*)d_in[0];
    const float* h0 = (const float*)d_in[1];
    const float* Wf = (const float*)d_in[2];
    const float* bf = (const float*)d_in[3];
    const float* Wi = (const float*)d_in[4];
    const float* bi = (const float*)d_in[5];
    const float* Wh = (const float*)d_in[6];
    const float* bh = (const float*)d_in[7];
    float* out = (float*)d_out;

    const int M = in_sizes[0] / D_DIM;   // 32768
    const int B = M / T_DIM;             // 8

    cudaFuncSetAttribute(gemm_epi, cudaFuncAttributeMaxDynamicSharedMemorySize,
                         GEMM_SMEM);

    const size_t nx = (size_t)M * D_DIM;          // 33.55M
    const size_t nw = (size_t)H_DIM * D_DIM;      // 1.05M
    const size_t ntot = nx + 3 * nw;              // 36.7M, /8/256 = 17920 blocks
    to_bf16_all<<<(int)(ntot / (8 * 256)), 256>>>(x, Wf, Wi, Wh, nx, nw);

    dim3 gGemm(H_DIM / BN, M / BM);      // (16, 256)
    gemm_epi<<<gGemm, 512, GEMM_SMEM>>>(bf, bi, bh);

    const int nChanThreads = B * H_DIM;
    scan_across<<<nChanThreads / 128, 128>>>(h0, B);

    const int nFinalThreads = B * CHUNKS * (H_DIM / 4);   // 65536
    scan_final<<<nFinalThreads / 256, 256>>>(out, B);
}

// round 14
// speedup vs baseline: 1.0336x; 1.0336x over previous
#include <cuda_runtime.h>
#include <cuda_bf16.h>
#include <math.h>
#include <stdint.h>

#define T_DIM 4096
#define D_DIM 1024
#define H_DIM 1024
#define B_MAX 8

#define CHUNKS 32
#define CLEN   (T_DIM / CHUNKS)   // 128

// ---------------- scratch (device globals) -----------------------------------
__device__ __align__(16) float2 g_lfv[(size_t)B_MAX * T_DIM * H_DIM];  // 268MB
__device__ float g_cA[(size_t)B_MAX * CHUNKS * H_DIM];
__device__ float g_cB[(size_t)B_MAX * CHUNKS * H_DIM];
__device__ float g_cS[(size_t)B_MAX * CHUNKS * H_DIM];
__device__ __align__(16) __nv_bfloat16 g_xbf[(size_t)B_MAX * T_DIM * D_DIM]; // 64MB
__device__ __align__(16) __nv_bfloat16 g_wbf[3][(size_t)H_DIM * D_DIM];      // 6MB

// ---------------- math helpers (MUFU fast path) --------------------------------
__device__ __forceinline__ float splus(float x) {
    return fmaxf(x, 0.0f) + __logf(1.0f + __expf(-fabsf(x)));
}
__device__ __forceinline__ float lae(float a, float b) {
    float m = fmaxf(a, b);
    float d = fabsf(a - b);
    return m + __logf(1.0f + __expf(-d));
}
__device__ __forceinline__ float log_g(float x) {
    return (x >= 0.0f) ? __logf(x + 0.5f) : -splus(-x);
}
__device__ __forceinline__ uint32_t bf16x2(float lo, float hi) {
    uint32_t r;
    asm("cvt.rn.bf16x2.f32 %0, %1, %2;" : "=r"(r) : "f"(hi), "f"(lo));
    return r;
}
__device__ __forceinline__ uint32_t smem_u32(const void* p) {
    uint32_t a;
    asm("{ .reg .u64 t; cvta.to.shared.u64 t, %1; cvt.u32.u64 %0, t; }" : "=r"(a) : "l"(p));
    return a;
}

// granule (row, kb) -> byte offset inside one operand tile (64B rows, rot-swizzle)
__device__ __forceinline__ uint32_t goff(int row, int kb) {
    return (uint32_t)(row * 64 + (((kb + (row >> 1)) & 3) << 4));
}

#define LDSM_X4(r0, r1, r2, r3, addr)                                            \
    asm volatile("ldmatrix.sync.aligned.m8n8.x4.shared.b16 {%0,%1,%2,%3}, [%4];" \
                 : "=r"(r0), "=r"(r1), "=r"(r2), "=r"(r3) : "r"(addr))

#define CP16(dst, src)                                                           \
    asm volatile("cp.async.cg.shared.global [%0], [%1], 16;"                     \
                 :: "r"(dst), "l"(src) : "memory")

// ---------------- merged convert fp32 -> bf16 (x then Wf,Wi,Wh) ----------------
__global__ void __launch_bounds__(256)
to_bf16_all(const float* __restrict__ x, const float* __restrict__ w0,
            const float* __restrict__ w1, const float* __restrict__ w2,
            size_t nx, size_t nw)
{
    const size_t i8 = ((size_t)blockIdx.x * blockDim.x + threadIdx.x) * 8;
    const float* src;
    __nv_bfloat16* dst;
    size_t off;
    if (i8 < nx) {
        src = x; dst = g_xbf; off = i8;
    } else {
        const size_t j = i8 - nx;
        const int gate = (int)(j / nw);
        off = j - (size_t)gate * nw;
        const float* ws[3] = {w0, w1, w2};
        src = ws[gate]; dst = g_wbf[gate];
    }
    float4 a = *(const float4*)(src + off);
    float4 b = *(const float4*)(src + off + 4);
    uint4 o;
    o.x = bf16x2(a.x, a.y);
    o.y = bf16x2(a.z, a.w);
    o.z = bf16x2(b.x, b.y);
    o.w = bf16x2(b.z, b.w);
    *(uint4*)(dst + off) = o;
}

// ---------------- bf16 TC fused 3-gate GEMM, 2 decoupled pipeline groups -------
#define BM 128
#define BN 64
#define BK 32
#define STAGES 4
#define GSTAGE_SZ 16384u    // per group per stage: A 4KB @0, W[g] 4KB @4096+g*4096
#define GROUP_SZ  (STAGES * GSTAGE_SZ)       // 64KB per group
#define GEMM_SMEM (2 * GROUP_SZ)             // 128KB
// epilogue SMEM reuse (floats): sF [128][65] @0, sV @33280, pA @66560, pB @68608

__global__ void __launch_bounds__(512, 1)
gemm_epi(const float* __restrict__ bf,
         const float* __restrict__ bi,
         const float* __restrict__ bh)
{
    extern __shared__ __align__(128) uint8_t smem[];
    const uint32_t sbase = smem_u32(smem);

    const int tid  = threadIdx.x;
    const int lane = tid & 31;
    const int wid  = tid >> 5;         // 0..15
    const int g    = lane >> 2;
    const int t    = lane & 3;

    const int group = wid >> 3;        // 0: rows 0-63, 1: rows 64-127
    const uint32_t gb = sbase + (uint32_t)group * GROUP_SZ;

    const int m0 = blockIdx.y * BM;
    const int n0 = blockIdx.x * BN;

    const int warpM = (wid >> 1) * 16;         // 0..112 step 16
    const int warpMloc = warpM & 63;
    const int warpN = (wid & 1) * 32;          // 0,32

    const int lrow = ((lane >> 3) & 1) * 8 + (lane & 7);
    const int lkb  = lane >> 4;
    const uint32_t aAddr = gb + goff(warpMloc + lrow, lkb);
    uint32_t bAddr[3][2];
#pragma unroll
    for (int gt = 0; gt < 3; gt++)
#pragma unroll
        for (int h = 0; h < 2; h++)
            bAddr[gt][h] = gb + 4096 + gt * 4096 + goff(warpN + h * 16 + lrow, lkb);

    const int ltid = tid & 255;
    const __nv_bfloat16* lsrc[4];
    uint32_t ldst[4];
#pragma unroll
    for (int j = 0; j < 4; j++) {
        const int q = ltid + j * 256;          // 0..1023
        if (q < 256) {
            const int row = q >> 2, kb = q & 3;
            lsrc[j] = g_xbf + (size_t)(m0 + group * 64 + row) * D_DIM + kb * 8;
            ldst[j] = gb + goff(row, kb);
        } else {
            const int p = q - 256;
            const int gate = p >> 8, row = (p >> 2) & 63, kb = p & 3;
            lsrc[j] = g_wbf[gate] + (size_t)(n0 + row) * D_DIM + kb * 8;
            ldst[j] = gb + 4096 + gate * 4096 + goff(row, kb);
        }
    }

    float acc[3][4][4];
#pragma unroll
    for (int gt = 0; gt < 3; gt++)
#pragma unroll
        for (int nt = 0; nt < 4; nt++)
#pragma unroll
            for (int c = 0; c < 4; c++) acc[gt][nt][c] = 0.0f;

    const int NT = D_DIM / BK;   // 32
    const int barid = group + 1;

#define LOAD_STAGE(st, kt)                                                     \
    {                                                                          \
        const uint32_t so = (uint32_t)(st) * GSTAGE_SZ;                        \
        const int ko = (kt) * BK;                                              \
        CP16(ldst[0] + so, lsrc[0] + ko);                                      \
        CP16(ldst[1] + so, lsrc[1] + ko);                                      \
        CP16(ldst[2] + so, lsrc[2] + ko);                                      \
        CP16(ldst[3] + so, lsrc[3] + ko);                                      \
    }

#pragma unroll
    for (int s = 0; s < STAGES - 1; s++) {
        LOAD_STAGE(s, s);
        asm volatile("cp.async.commit_group;" ::: "memory");
    }

    for (int kt = 0; kt < NT; kt++) {
        const uint32_t sel = (uint32_t)(kt % STAGES) * GSTAGE_SZ;

        asm volatile("cp.async.wait_group %0;" :: "n"(STAGES - 2) : "memory");
        asm volatile("bar.sync %0, 256;" :: "r"(barid) : "memory");

#pragma unroll
        for (int s = 0; s < 2; s++) {
            const uint32_t sx = (uint32_t)(s << 5);
            uint32_t a[4];
            LDSM_X4(a[0], a[1], a[2], a[3], (aAddr ^ sx) + sel);
#pragma unroll
            for (int gt = 0; gt < 3; gt++) {
                uint32_t bb[2][4];
#pragma unroll
                for (int h = 0; h < 2; h++)
                    LDSM_X4(bb[h][0], bb[h][1], bb[h][2], bb[h][3],
                            (bAddr[gt][h] ^ sx) + sel);
#pragma unroll
                for (int nt = 0; nt < 4; nt++) {
                    float* c = acc[gt][nt];
                    const uint32_t b0 = bb[nt >> 1][nt & 1];
                    const uint32_t b1 = bb[nt >> 1][(nt & 1) + 2];
                    asm volatile(
                        "mma.sync.aligned.m16n8k16.row.col.f32.bf16.bf16.f32 "
                        "{%0,%1,%2,%3}, {%4,%5,%6,%7}, {%8,%9}, {%0,%1,%2,%3};"
                        : "+f"(c[0]), "+f"(c[1]), "+f"(c[2]), "+f"(c[3])
                        : "r"(a[0]), "r"(a[1]), "r"(a[2]), "r"(a[3]),
                          "r"(b0), "r"(b1));
                }
            }
        }

        if (kt + STAGES - 1 < NT)
            LOAD_STAGE((kt + STAGES - 1) % STAGES, kt + STAGES - 1);
        asm volatile("cp.async.commit_group;" ::: "memory");
    }

    // ---- epilogue: bias + gate math -> g_lfv + in-SMEM chunk aggregation ----
    float* sF = (float*)smem;                     // [128][65]
    float* sV = (float*)(smem + 33280);           // [128][65]
    float* pA = (float*)(smem + 66560);           // [8][64]
    float* pB = (float*)(smem + 68608);

    float bfv[4][2], biv[4][2], bhv[4][2];
#pragma unroll
    for (int nt = 0; nt < 4; nt++)
#pragma unroll
        for (int e = 0; e < 2; e++) {
            const int n = n0 + warpN + nt * 8 + 2 * t + e;
            bfv[nt][e] = bf[n];
            biv[nt][e] = bi[n];
            bhv[nt][e] = bh[n];
        }

    __syncthreads();   // join both groups; all LDSM reads done before SMEM reuse

#pragma unroll
    for (int hh = 0; hh < 2; hh++) {
        const int lt = warpM + hh * 8 + g;              // local row 0..127
        const size_t rowoff = (size_t)(m0 + lt) * H_DIM + n0 + warpN;
#pragma unroll
        for (int nt = 0; nt < 4; nt++) {
#pragma unroll
            for (int e = 0; e < 2; e++) {
                const int ci = hh * 2 + e;
                float zf = acc[0][nt][ci] + bfv[nt][e];
                float zi = acc[1][nt][ci] + biv[nt][e];
                float zh = acc[2][nt][ci] + bhv[nt][e];
                float diff  = splus(-zf) - splus(-zi);
                float logF  = -splus(diff);
                float logV  = -splus(-diff) + log_g(zh);
                const int ln = warpN + nt * 8 + 2 * t + e;   // local col 0..63
                g_lfv[rowoff + nt * 8 + 2 * t + e] = make_float2(logF, logV);
                sF[lt * 65 + ln] = logF;
                sV[lt * 65 + ln] = logV;
            }
        }
    }
    __syncthreads();

    // segmented scan: 64 cols x 8 segments of 16
    {
        const int col = tid & 63;
        const int seg = tid >> 6;
        const int base = seg * 16;
        float A  = sF[base * 65 + col];
        float Bv = sV[base * 65 + col];
#pragma unroll
        for (int i = 1; i < 16; i++) {
            const float a  = sF[(base + i) * 65 + col];
            const float b  = sV[(base + i) * 65 + col];
            A += a;
            Bv = lae(Bv + a, b);
        }
        pA[seg * 64 + col] = A;
        pB[seg * 64 + col] = Bv;
    }
    __syncthreads();

    if (tid < 64) {
        float A  = pA[tid];
        float Bv = pB[tid];
#pragma unroll
        for (int s = 1; s < 8; s++) {
            const float a = pA[s * 64 + tid];
            const float b = pB[s * 64 + tid];
            Bv = lae(Bv + a, b);
            A += a;
        }
        const size_t co = (size_t)blockIdx.y * H_DIM + n0 + tid;
        g_cA[co] = A;
        g_cB[co] = Bv;
    }
}

// ---------------- pass 2: scan across chunks (prefetch-then-scan) -------------
__global__ void __launch_bounds__(256)
scan_across(const float* __restrict__ h0, int B)
{
    const size_t gid = (size_t)blockIdx.x * blockDim.x + threadIdx.x;
    const int h = (int)(gid % H_DIM);
    const int b = (int)(gid / H_DIM);
    if (b >= B) return;

    const size_t base = (size_t)b * CHUNKS * H_DIM + h;

    float vA[CHUNKS], vB[CHUNKS];
#pragma unroll
    for (int c = 0; c < CHUNKS; c++) {
        vA[c] = g_cA[base + (size_t)c * H_DIM];
        vB[c] = g_cB[base + (size_t)c * H_DIM];
    }

    float state = log_g(h0[(size_t)b * H_DIM + h]);
#pragma unroll
    for (int c = 0; c < CHUNKS; c++) {
        g_cS[base + (size_t)c * H_DIM] = state;
        state = lae(state + vA[c], vB[c]);
    }
}

// ---------------- pass 3: final within-chunk scan + exp (2 cols/thread) -------
__global__ void __launch_bounds__(256)
scan_final(float* __restrict__ out, int B)
{
    const size_t gid = (size_t)blockIdx.x * blockDim.x + threadIdx.x;
    const int hp = (int)(gid % (H_DIM / 2));
    const int h  = hp * 2;
    const size_t bc = gid / (H_DIM / 2);
    const int c = (int)(bc % CHUNKS);
    const int b = (int)(bc / CHUNKS);
    if (b >= B) return;

    const size_t co = ((size_t)b * CHUNKS + c) * H_DIM + h;
    float s0 = g_cS[co];
    float s1 = g_cS[co + 1];

    size_t idx = ((size_t)b * T_DIM + (size_t)c * CLEN) * H_DIM + h;
#pragma unroll 4
    for (int tt = 0; tt < CLEN; tt++) {
        const float4 v = *(const float4*)&g_lfv[idx];   // {f0,v0,f1,v1}
        s0 = lae(s0 + v.x, v.y);
        s1 = lae(s1 + v.z, v.w);
        float2 ov;
        ov.x = __expf(s0);
        ov.y = __expf(s1);
        *(float2*)(out + idx) = ov;
        idx += H_DIM;
    }
}

// ---------------- launch --------------------------------------------------------
extern "C" void kernel_launch(void* const* d_in, const int* in_sizes, int n_in,
                              void* d_out, int out_size)
{
    const float* x  = (const float*)d_in[0];
    const float* h0 = (const float*)d_in[1];
    const float* Wf = (const float*)d_in[2];
    const float* bf = (const float*)d_in[3];
    const float* Wi = (const float*)d_in[4];
    const float* bi = (const float*)d_in[5];
    const float* Wh = (const float*)d_in[6];
    const float* bh = (const float*)d_in[7];
    float* out = (float*)d_out;

    const int M = in_sizes[0] / D_DIM;   // 32768
    const int B = M / T_DIM;             // 8

    cudaFuncSetAttribute(gemm_epi, cudaFuncAttributeMaxDynamicSharedMemorySize,
                         GEMM_SMEM);

    const size_t nx = (size_t)M * D_DIM;          // 33.55M
    const size_t nw = (size_t)H_DIM * D_DIM;      // 1.05M
    const size_t ntot = nx + 3 * nw;              // 36.7M
    to_bf16_all<<<(int)(ntot / (8 * 256)), 256>>>(x, Wf, Wi, Wh, nx, nw);

    dim3 gGemm(H_DIM / BN, M / BM);      // (16, 256)
    gemm_epi<<<gGemm, 512, GEMM_SMEM>>>(bf, bi, bh);

    const int nChanThreads = B * H_DIM;
    scan_across<<<nChanThreads / 256, 256>>>(h0, B);

    const int nFinalThreads = B * CHUNKS * (H_DIM / 2);   // 131072
    scan_final<<<nFinalThreads / 256, 256>>>(out, B);
}